// round 4
// baseline (speedup 1.0000x reference)
#include <cuda_runtime.h>
#include <math.h>

// Problem constants (from reference):
//   BATCH=16, EMBED=50, L=M=50, N=1900, ITER=76, CSTRIDE=38
//   x_cnn: (16,36,36); out: (16,36,50); d_out = [out | x_cnn] = 28800 + 20736 floats
//
// Analytic collapse of the FFT pipeline:
//   |C[b,t,c]| = Qmag[c]*Pmag[t]*| sum_j psi(j,c)*|W[t,j]|*U[b,t,j] |
//   U[b,t,j]   = sum_i xcnn[b,i,j]*phi(i,t)
//   phi(i,t)   = exp(-i*pi*((50+2i)(2t-50) mod 200)/100)
//   psi(j,c)   = exp(-i*pi*((76*j*(c+1)) mod 200)/100)
//   Pmag[t]    = |1 + exp(-i*pi*(2t-50)/100)|
//   Qmag[c]    = |sum_{q=0..75} exp(-i*pi*q*(c+1)/100)|
// Final: out[b,c,t] = |C[b,t,c]| / max_{t',c'}|C[b,t',c']| * imax[b]*wmax + bias[c,t]

#define THREADS 512

__device__ __forceinline__ float block_max(float v, float* s_red) {
    int tid = threadIdx.x;
    s_red[tid] = v;
    __syncthreads();
    #pragma unroll
    for (int off = THREADS / 2; off > 0; off >>= 1) {
        if (tid < off) s_red[tid] = fmaxf(s_red[tid], s_red[tid + off]);
        __syncthreads();
    }
    float r = s_red[0];
    __syncthreads();
    return r;
}

__global__ void __launch_bounds__(THREADS)
ocnn_kernel(const float* __restrict__ x,      // (16,1,28,28)
            const float* __restrict__ w,      // (50,36)
            const float* __restrict__ bias,   // (1,36,50)
            float* __restrict__ out)          // [ (16,36,50) | (16,36,36) ]
{
    __shared__ float s_x[36 * 36];        // x_cnn for this batch
    __shared__ float s_W[50 * 36];        // |weight|
    __shared__ float s_A[50 * 36 * 2];    // phi table, then reused as psi table
    __shared__ float s_B[50 * 36 * 2];    // W*U (complex, interleaved)
    __shared__ float s_P[50];
    __shared__ float s_Q[50];
    __shared__ float s_red[THREADS];

    const int b   = blockIdx.x;
    const int tid = threadIdx.x;
    const float* xb = x + b * 784;        // 28*28

    // ---- x_cnn (im2col with pad (1,2)) + write second output tensor ----
    // x_cnn[R=6a+p, C=6c+d] = xp[5a+c, 5p+d],  xp = pad(x, (1,2))
    for (int idx = tid; idx < 1296; idx += THREADS) {
        int R = idx / 36, Cc = idx % 36;
        int r  = 5 * (R / 6) + Cc / 6;    // 0..30
        int cc = 5 * (R % 6) + Cc % 6;    // 0..30
        float v = 0.f;
        if (r >= 1 && r <= 28 && cc >= 1 && cc <= 28)
            v = xb[(r - 1) * 28 + (cc - 1)];
        s_x[idx] = v;
        out[28800 + b * 1296 + idx] = v;
    }
    for (int idx = tid; idx < 1800; idx += THREADS)
        s_W[idx] = fabsf(w[idx]);

    // ---- phi table: s_A[t][i] = exp(-i*pi*k/100), k=((50+2i)(2t-50)) mod 200 ----
    for (int idx = tid; idx < 1800; idx += THREADS) {
        int t = idx / 36, i = idx % 36;
        int k = ((50 + 2 * i) * (2 * t - 50)) % 200;
        if (k < 0) k += 200;
        float sn, cs;
        sincospif((float)k * 0.01f, &sn, &cs);
        s_A[2 * idx]     = cs;
        s_A[2 * idx + 1] = -sn;
    }
    // ---- Pmag, Qmag ----
    if (tid < 50) {
        s_P[tid] = 2.f * fabsf(cospif((float)(tid - 25) * 0.01f));
        int cp1 = tid + 1;
        float qr = 0.f, qi = 0.f;
        for (int q = 0; q < 76; q++) {
            int m = (q * cp1) % 200;
            float sn, cs;
            sincospif((float)m * 0.01f, &sn, &cs);
            qr += cs;
            qi -= sn;
        }
        s_Q[tid] = sqrtf(qr * qr + qi * qi);
    }
    __syncthreads();

    // ---- imax (padded inp includes zeros -> init 0), wmax ----
    float lm = 0.f;
    for (int idx = tid; idx < 1296; idx += THREADS) lm = fmaxf(lm, s_x[idx]);
    float imax = block_max(lm, s_red);
    float lw = 0.f;
    for (int idx = tid; idx < 1800; idx += THREADS) lw = fmaxf(lw, s_W[idx]);
    float wmax = block_max(lw, s_red);

    // ---- WU[t][j] = |W[t,j]| * sum_i xcnn[i,j]*phi(i,t) ----
    for (int idx = tid; idx < 1800; idx += THREADS) {
        int t = idx / 36, j = idx % 36;
        const float* ph = &s_A[2 * 36 * t];
        float ur = 0.f, ui = 0.f;
        #pragma unroll
        for (int i = 0; i < 36; i++) {
            float xv = s_x[i * 36 + j];
            ur = fmaf(xv, ph[2 * i],     ur);
            ui = fmaf(xv, ph[2 * i + 1], ui);
        }
        float wv = s_W[idx];
        s_B[2 * idx]     = ur * wv;
        s_B[2 * idx + 1] = ui * wv;
    }
    __syncthreads();

    // ---- psi table overwrites phi: s_A[c][j] = exp(-i*pi*m/100), m=(76 j (c+1)) mod 200 ----
    for (int idx = tid; idx < 1800; idx += THREADS) {
        int c = idx / 36, j = idx % 36;
        int m = (76 * j * (c + 1)) % 200;
        float sn, cs;
        sincospif((float)m * 0.01f, &sn, &cs);
        s_A[2 * idx]     = cs;
        s_A[2 * idx + 1] = -sn;
    }
    __syncthreads();

    // ---- pass A: max |T| over full 50x50 (t,c) grid ----
    float lT = 0.f;
    for (int idx = tid; idx < 2500; idx += THREADS) {
        int t = idx / 50, c = idx % 50;
        const float* ps = &s_A[2 * 36 * c];
        const float* wu = &s_B[2 * 36 * t];
        float vr = 0.f, vi = 0.f;
        #pragma unroll
        for (int j = 0; j < 36; j++) {
            float pr = ps[2 * j], pi = ps[2 * j + 1];
            float wr = wu[2 * j], wi = wu[2 * j + 1];
            vr += pr * wr - pi * wi;
            vi += pr * wi + pi * wr;
        }
        float a = s_Q[c] * s_P[t] * sqrtf(vr * vr + vi * vi);
        lT = fmaxf(lT, a);
    }
    float maxT  = block_max(lT, s_red);
    float scale = imax * wmax / maxT;

    // ---- pass B: out[b, c, t] for c<36, t<50 ----
    float* ob = out + b * 1800;
    for (int idx = tid; idx < 1800; idx += THREADS) {
        int c = idx / 50, t = idx % 50;
        const float* ps = &s_A[2 * 36 * c];
        const float* wu = &s_B[2 * 36 * t];
        float vr = 0.f, vi = 0.f;
        #pragma unroll
        for (int j = 0; j < 36; j++) {
            float pr = ps[2 * j], pi = ps[2 * j + 1];
            float wr = wu[2 * j], wi = wu[2 * j + 1];
            vr += pr * wr - pi * wi;
            vi += pr * wi + pi * wr;
        }
        float a = s_Q[c] * s_P[t] * sqrtf(vr * vr + vi * vi);
        ob[idx] = a * scale + bias[idx];
    }
}

extern "C" void kernel_launch(void* const* d_in, const int* in_sizes, int n_in,
                              void* d_out, int out_size)
{
    const float* x    = (const float*)d_in[0];  // (16,1,28,28)
    const float* w    = (const float*)d_in[1];  // (50,36)
    const float* bias = (const float*)d_in[2];  // (1,36,50)
    float* out = (float*)d_out;                 // 49536 floats
    ocnn_kernel<<<16, THREADS>>>(x, w, bias, out);
}

// round 5
// speedup vs baseline: 1.7802x; 1.7802x over previous
#include <cuda_runtime.h>
#include <math.h>

// Analytic collapse of the reference 4f-correlator FFT pipeline (verified, rel_err 3e-7):
//   |C[b,t,c]| = Qmag[c]*Pmag[t]*| sum_j psi(j,c)*|W[t,j]|*U[b,t,j] |
//   U[b,t,j]   = sum_i xcnn[b,i,j]*phi(i,t)
//   phi(i,t)   = tw[((50+2i)(2t-50)) mod 200],  tw[k] = exp(-i*pi*k/100)
//   psi(j,c)   = tw[(76*j*(c+1)) mod 200]
//   Pmag[t]    = 2|cos(pi*(t-25)/100)|
//   Qmag[c]    = |sin(pi*38(c+1)/100)| / |sin(pi*(c+1)/200)|   (geometric series)
// out[b,c,t] = |C[b,t,c]| / max|C[b]| * imax[b]*wmax + bias[c,t];  then x_cnn appended.

#define THREADS 512
#define PHS 37            // padded row stride (float2) for the phi/psi table

// Block-wide max via warp shuffles. Each call must use a distinct 16-float region.
__device__ __forceinline__ float bmax(float v, float* reg16) {
    #pragma unroll
    for (int o = 16; o; o >>= 1)
        v = fmaxf(v, __shfl_xor_sync(0xffffffffu, v, o));
    int wid = threadIdx.x >> 5, lane = threadIdx.x & 31;
    if (lane == 0) reg16[wid] = v;
    __syncthreads();
    if (threadIdx.x < 32) {
        float r = reg16[lane & 15];
        #pragma unroll
        for (int o = 8; o; o >>= 1)
            r = fmaxf(r, __shfl_xor_sync(0xffffffffu, r, o));
        if (lane == 0) reg16[0] = r;
    }
    __syncthreads();
    return reg16[0];
}

__global__ void __launch_bounds__(THREADS)
ocnn_kernel(const float* __restrict__ x,      // (16,1,28,28)
            const float* __restrict__ w,      // (50,36)
            const float* __restrict__ bias,   // (1,36,50)
            float* __restrict__ out)          // [ (16,36,50) | (16,36,36) ]
{
    __shared__ float  s_x[1296];          // x_cnn
    __shared__ float2 s_A[50 * PHS];      // phi table, then reused as psi table
    __shared__ float2 s_B[50 * 36];       // WU (complex)
    __shared__ float  s_T[2500];          // |C|[t][c]
    __shared__ float2 s_tw[200];          // exp(-i*pi*k/100)
    __shared__ float  s_P[50], s_Q[50];
    __shared__ float  s_red[48];          // 3 x 16 reduction slots

    const int b = blockIdx.x, tid = threadIdx.x;
    const float* xb = x + b * 784;

    // ---- P0: twiddles, P/Q closed forms, im2col (+ second output tensor) ----
    if (tid < 200) {
        float sn, cs;
        sincospif((float)tid * 0.01f, &sn, &cs);
        s_tw[tid] = make_float2(cs, -sn);
    }
    if (tid >= 256 && tid < 306) {
        int t = tid - 256;
        s_P[t] = 2.f * fabsf(cospif((float)(t - 25) * 0.01f));
        float num = fabsf(sinpif((float)(38 * (t + 1)) * 0.01f));
        float den = fabsf(sinpif((float)(t + 1) * 0.005f));
        s_Q[t] = num / den;
    }
    for (int idx = tid; idx < 1296; idx += THREADS) {
        int R = idx / 36, Cc = idx % 36;
        int r  = 5 * (R / 6) + Cc / 6;
        int cc = 5 * (R % 6) + Cc % 6;
        float v = 0.f;
        if (r >= 1 && r <= 28 && cc >= 1 && cc <= 28)
            v = xb[(r - 1) * 28 + (cc - 1)];
        s_x[idx] = v;
        out[28800 + b * 1296 + idx] = v;
    }
    __syncthreads();

    // ---- P1: phi table + imax/wmax ----
    for (int idx = tid; idx < 1800; idx += THREADS) {
        int t = idx / 36, i = idx % 36;
        int k = ((50 + 2 * i) * (2 * t - 50)) % 200;
        if (k < 0) k += 200;
        s_A[t * PHS + i] = s_tw[k];
    }
    float lm = 0.f, lw = 0.f;
    for (int idx = tid; idx < 1296; idx += THREADS) lm = fmaxf(lm, s_x[idx]);
    for (int idx = tid; idx < 1800; idx += THREADS) lw = fmaxf(lw, fabsf(w[idx]));
    float imax = bmax(lm, s_red);        // syncs also fence phi writes
    float wmax = bmax(lw, s_red + 16);

    // ---- P2: WU[t][j] = |W[t,j]| * sum_i xcnn[i,j]*phi(i,t) ----
    for (int idx = tid; idx < 1800; idx += THREADS) {
        int t = idx / 36, j = idx % 36;
        const float2* ph = &s_A[t * PHS];
        const float*  xc = &s_x[j];
        float ur0 = 0.f, ui0 = 0.f, ur1 = 0.f, ui1 = 0.f;
        #pragma unroll
        for (int i = 0; i < 36; i += 2) {
            float  x0 = xc[i * 36], x1 = xc[(i + 1) * 36];
            float2 p0 = ph[i],      p1 = ph[i + 1];
            ur0 = fmaf(x0, p0.x, ur0); ui0 = fmaf(x0, p0.y, ui0);
            ur1 = fmaf(x1, p1.x, ur1); ui1 = fmaf(x1, p1.y, ui1);
        }
        float wv = fabsf(w[idx]);
        s_B[idx] = make_float2((ur0 + ur1) * wv, (ui0 + ui1) * wv);
    }
    __syncthreads();

    // ---- P3: psi table overwrites phi ----
    for (int idx = tid; idx < 1800; idx += THREADS) {
        int c = idx / 36, j = idx % 36;
        int m = (76 * j * (c + 1)) % 200;
        s_A[c * PHS + j] = s_tw[m];
    }
    __syncthreads();

    // ---- P4: register-blocked pass A over full 50x50 grid -> s_T + max ----
    float lT = 0.f;
    if (tid < 500) {
        int t = tid / 10, c0 = (tid % 10) * 5;
        const float2* wu = &s_B[t * 36];      // same t for 10 lanes -> LDS broadcast
        const float2* ps = &s_A[c0 * PHS];
        float vr[5], vi[5];
        #pragma unroll
        for (int cc = 0; cc < 5; cc++) { vr[cc] = 0.f; vi[cc] = 0.f; }
        #pragma unroll 4
        for (int j = 0; j < 36; j++) {
            float2 u = wu[j];
            #pragma unroll
            for (int cc = 0; cc < 5; cc++) {
                float2 p = ps[cc * PHS + j];
                vr[cc] = fmaf(p.x, u.x, vr[cc]);
                vr[cc] = fmaf(-p.y, u.y, vr[cc]);
                vi[cc] = fmaf(p.x, u.y, vi[cc]);
                vi[cc] = fmaf(p.y, u.x, vi[cc]);
            }
        }
        float pt = s_P[t];
        #pragma unroll
        for (int cc = 0; cc < 5; cc++) {
            float a = s_Q[c0 + cc] * pt * sqrtf(vr[cc] * vr[cc] + vi[cc] * vi[cc]);
            s_T[t * 50 + c0 + cc] = a;
            lT = fmaxf(lT, a);
        }
    }
    float maxT = bmax(lT, s_red + 32);    // syncs also fence s_T writes
    float scale = imax * wmax / maxT;

    // ---- P5: out[b,c,t] = s_T[t][c]*scale + bias ----
    float* ob = out + b * 1800;
    for (int idx = tid; idx < 1800; idx += THREADS) {
        int c = idx / 50, t = idx % 50;
        ob[idx] = s_T[t * 50 + c] * scale + bias[idx];
    }
}

extern "C" void kernel_launch(void* const* d_in, const int* in_sizes, int n_in,
                              void* d_out, int out_size)
{
    const float* x    = (const float*)d_in[0];  // (16,1,28,28)
    const float* w    = (const float*)d_in[1];  // (50,36)
    const float* bias = (const float*)d_in[2];  // (1,36,50)
    float* out = (float*)d_out;                 // 49536 floats
    ocnn_kernel<<<16, THREADS>>>(x, w, bias, out);
}

// round 6
// speedup vs baseline: 2.2649x; 1.2723x over previous
#include <cuda_runtime.h>
#include <math.h>

// Analytic collapse of the reference 4f-correlator FFT pipeline (verified, rel_err 3e-7):
//   |C[b,t,c]| = Qmag[c]*Pmag[t]*| sum_j psi(j,c)*|W[t,j]|*U[b,t,j] |
//   U[b,t,j]   = sum_i xcnn[b,i,j]*phi(i,t)
//   phi(i,t)   = tw[((50+2i)(2t-50)) mod 200],  tw[k] = exp(-i*pi*k/100)
//   psi(j,c)   = tw[(76*j*(c+1)) mod 200]
//   Pmag[t]    = 2|cos(pi*(t-25)/100)|
//   Qmag[c]    = |sin(pi*38(c+1)/100)| / |sin(pi*(c+1)/200)|   (geometric series)
// out[b,c,t] = |C[b,t,c]| / max|C[b]| * imax[b]*wmax + bias[c,t];  then x_cnn appended.
//
// R6 structure: split each batch's (t,c) grid over SPLIT=8 blocks (grid=128 ~ one
// full wave on 148 SMs), scratch |C| + partial maxes in __device__ globals, tiny
// second kernel does the max-combine + scale + bias + transpose.

#define THREADS 512
#define SPLIT   8
#define TCHUNK  7          // ceil(50/8); last slice handles 1 row
#define PHS     37         // padded row stride (float2) for the psi table

__device__ float g_T[16 * 2500];      // |C|[b][t][c]
__device__ float g_pmax[16 * SPLIT];  // per-slice partial max
__device__ float g_iw[16];            // imax[b] * wmax

__device__ __forceinline__ float bmax(float v, float* reg16) {
    #pragma unroll
    for (int o = 16; o; o >>= 1)
        v = fmaxf(v, __shfl_xor_sync(0xffffffffu, v, o));
    int wid = threadIdx.x >> 5, lane = threadIdx.x & 31;
    if (lane == 0) reg16[wid] = v;
    __syncthreads();
    if (threadIdx.x < 32) {
        float r = reg16[lane & 15];
        #pragma unroll
        for (int o = 8; o; o >>= 1)
            r = fmaxf(r, __shfl_xor_sync(0xffffffffu, r, o));
        if (lane == 0) reg16[0] = r;
    }
    __syncthreads();
    return reg16[0];
}

__global__ void __launch_bounds__(THREADS)
ocnn_k1(const float* __restrict__ x,      // (16,1,28,28)
        const float* __restrict__ w,      // (50,36)
        float* __restrict__ out)          // writes x_cnn tail only (slice 0)
{
    __shared__ float  s_x[1296];
    __shared__ float2 s_tw[200];
    __shared__ float2 s_psi[50 * PHS];
    __shared__ float2 s_B[TCHUNK * 36];   // WU for this slice's t rows
    __shared__ float  s_Q[50];
    __shared__ float  s_red[16];

    const int b   = blockIdx.x >> 3;
    const int s   = blockIdx.x & (SPLIT - 1);
    const int t0  = s * TCHUNK;
    const int t1  = (t0 + TCHUNK < 50) ? t0 + TCHUNK : 50;
    const int nt  = t1 - t0;
    const int tid = threadIdx.x;
    const float* xb = x + b * 784;

    // ---- P0: twiddles, Q, im2col ----
    if (tid < 200) {
        float sn, cs;
        sincospif((float)tid * 0.01f, &sn, &cs);
        s_tw[tid] = make_float2(cs, -sn);
    }
    if (tid >= 256 && tid < 306) {
        int c = tid - 256;
        float num = fabsf(sinpif((float)(38 * (c + 1)) * 0.01f));
        float den = fabsf(sinpif((float)(c + 1) * 0.005f));
        s_Q[c] = num / den;
    }
    for (int idx = tid; idx < 1296; idx += THREADS) {
        int R = idx / 36, Cc = idx % 36;
        int r  = 5 * (R / 6) + Cc / 6;
        int cc = 5 * (R % 6) + Cc % 6;
        float v = 0.f;
        if (r >= 1 && r <= 28 && cc >= 1 && cc <= 28)
            v = xb[(r - 1) * 28 + (cc - 1)];
        s_x[idx] = v;
        if (s == 0) out[28800 + b * 1296 + idx] = v;
    }
    __syncthreads();

    // ---- P1 (concurrent thread ranges): WU for this slice  |  psi table ----
    if (tid < nt * 36) {
        // WU[tl][j] = |W[t,j]| * sum_i x_cnn[i,j] * tw[(50+2i)(2t-50) mod 200]
        int tl = tid / 36, j = tid % 36;
        int t  = t0 + tl;
        int d  = 2 * t - 50;
        int k    = ((50 * d) % 200 + 200) % 200;   // i = 0 phase
        int step = ((2  * d) % 200 + 200) % 200;   // increment per i
        const float* xc = &s_x[j];
        float ur = 0.f, ui = 0.f;
        #pragma unroll
        for (int i = 0; i < 36; i++) {
            float2 p = s_tw[k];
            float  xv = xc[i * 36];
            ur = fmaf(xv, p.x, ur);
            ui = fmaf(xv, p.y, ui);
            k += step; if (k >= 200) k -= 200;
        }
        float wv = fabsf(w[t * 36 + j]);
        s_B[tid] = make_float2(ur * wv, ui * wv);
    } else {
        // psi[c][j] = tw[(76*j*(c+1)) mod 200], built by the remaining threads
        for (int idx = tid - nt * 36; idx < 1800; idx += THREADS - nt * 36) {
            int c = idx / 36, j = idx % 36;
            int m = (76 * j * (c + 1)) % 200;
            s_psi[c * PHS + j] = s_tw[m];
        }
    }
    // slice 0 additionally computes imax * wmax for the batch
    float liw = 0.f;
    if (s == 0) {
        float lm = 0.f, lw = 0.f;
        for (int idx = tid; idx < 1296; idx += THREADS) lm = fmaxf(lm, s_x[idx]);
        for (int idx = tid; idx < 1800; idx += THREADS) lw = fmaxf(lw, fabsf(w[idx]));
        liw = lm;  // reduce imax first, wmax folded below
        // two reductions folded into one pass: reduce (imax) then (wmax)
        float imax = bmax(lm, s_red);
        float wmax = bmax(lw, s_red);
        if (tid == 0) g_iw[b] = imax * wmax;
    } else {
        // keep sync counts identical across all blocks in the CTA? not needed —
        // syncthreads is per-block; slice!=0 blocks just sync once below.
    }
    __syncthreads();

    // ---- P2: pass A for nt*50 points -> g_T + per-slice partial max ----
    float lT = 0.f;
    if (tid < nt * 50) {
        int tl = tid / 50, c = tid % 50;
        int t  = t0 + tl;
        const float2* wu = &s_B[tl * 36];
        const float2* ps = &s_psi[c * PHS];
        float vr = 0.f, vi = 0.f;
        #pragma unroll
        for (int j = 0; j < 36; j++) {
            float2 u = wu[j];
            float2 p = ps[j];
            vr = fmaf(p.x, u.x, vr); vr = fmaf(-p.y, u.y, vr);
            vi = fmaf(p.x, u.y, vi); vi = fmaf( p.y, u.x, vi);
        }
        float pt = 2.f * fabsf(cospif((float)(t - 25) * 0.01f));
        float a  = s_Q[c] * pt * sqrtf(vr * vr + vi * vi);
        g_T[b * 2500 + t * 50 + c] = a;
        lT = a;
    }
    float pm = bmax(lT, s_red);
    if (tid == 0) g_pmax[b * SPLIT + s] = pm;
    (void)liw;
}

__global__ void __launch_bounds__(256)
ocnn_k2(const float* __restrict__ bias,   // (1,36,50)
        float* __restrict__ out)
{
    __shared__ float s_scale;
    const int b = blockIdx.x, tid = threadIdx.x;

    if (tid == 0) {
        float m = 0.f;
        #pragma unroll
        for (int i = 0; i < SPLIT; i++) m = fmaxf(m, g_pmax[b * SPLIT + i]);
        s_scale = g_iw[b] / m;
    }
    __syncthreads();
    float scale = s_scale;

    const float* Tb = &g_T[b * 2500];
    float* ob = out + b * 1800;
    for (int idx = tid; idx < 1800; idx += 256) {
        int c = idx / 50, t = idx % 50;
        ob[idx] = Tb[t * 50 + c] * scale + bias[idx];
    }
}

extern "C" void kernel_launch(void* const* d_in, const int* in_sizes, int n_in,
                              void* d_out, int out_size)
{
    const float* x    = (const float*)d_in[0];  // (16,1,28,28)
    const float* w    = (const float*)d_in[1];  // (50,36)
    const float* bias = (const float*)d_in[2];  // (1,36,50)
    float* out = (float*)d_out;                 // 49536 floats
    ocnn_k1<<<16 * SPLIT, THREADS>>>(x, w, out);
    ocnn_k2<<<16, 256>>>(bias, out);
}

// round 7
// speedup vs baseline: 2.3705x; 1.0466x over previous
#include <cuda_runtime.h>
#include <math.h>

// Analytic collapse of the reference 4f-correlator FFT pipeline (verified, rel_err 3e-7):
//   |C[b,t,c]| = Qmag[c]*Pmag[t]*| sum_j psi(j,c)*|W[t,j]|*U[b,t,j] |
//   U[b,t,j]   = sum_i xcnn[b,i,j]*phi(i,t)
//   phi(i,t)   = tw[((50+2i)(2t-50)) mod 200],  tw[k] = exp(-i*pi*k/100)
//   psi(j,c)   = tw[(76*j*(c+1)) mod 200]
//   Pmag[t]    = 2|cos(pi*(t-25)/100)|
//   Qmag[c]    = |sin(pi*38(c+1)/100)| / |sin(pi*(c+1)/200)|   (geometric series)
// out[b,c,t] = |C[b,t,c]| / max|C[b]| * imax[b]*wmax + bias[c,t];  then x_cnn appended.
//
// R7: single fused kernel. 16 batches x SPLIT=8 t-slices = 128 blocks <= 148 SMs
// -> whole grid co-resident in wave 1, so the per-batch max is combined with an
// atomicMax + counter handshake (spin-wait is deadlock-free). Slice results stay
// in smem; each block writes its own output rows. Counter/max reset by the last
// arrival -> replay-safe under CUDA-graph timing.

#define THREADS 512
#define SPLIT   8
#define TCHUNK  7          // slices 0..6: 7 t-rows, slice 7: 1 row
#define PHS     37         // padded row stride (float2) for the psi table

__device__ unsigned g_maxbits[16];   // per-batch max |C| as ordered uint (0-init)
__device__ unsigned g_cnt[16];       // per-batch arrival counter (0-init)

__device__ __forceinline__ float bmax(float v, float* reg16) {
    #pragma unroll
    for (int o = 16; o; o >>= 1)
        v = fmaxf(v, __shfl_xor_sync(0xffffffffu, v, o));
    int wid = threadIdx.x >> 5, lane = threadIdx.x & 31;
    if (lane == 0) reg16[wid] = v;
    __syncthreads();
    if (threadIdx.x < 32) {
        float r = reg16[lane & 15];
        #pragma unroll
        for (int o = 8; o; o >>= 1)
            r = fmaxf(r, __shfl_xor_sync(0xffffffffu, r, o));
        if (lane == 0) reg16[0] = r;
    }
    __syncthreads();
    return reg16[0];
}

__global__ void __launch_bounds__(THREADS)
ocnn_fused(const float* __restrict__ x,      // (16,1,28,28)
           const float* __restrict__ w,      // (50,36)
           const float* __restrict__ bias,   // (1,36,50)
           float* __restrict__ out)          // [ (16,36,50) | (16,36,36) ]
{
    __shared__ float  s_x[1296];
    __shared__ float2 s_tw[200];
    __shared__ float2 s_psi[50 * PHS];
    __shared__ float2 s_B[TCHUNK * 36];    // WU for this slice's t rows
    __shared__ float  s_T[TCHUNK * 50];    // |C| for this slice
    __shared__ float  s_Q[50];
    __shared__ float  s_red[16];
    __shared__ float  s_maxT;

    const int b   = blockIdx.x >> 3;
    const int s   = blockIdx.x & (SPLIT - 1);
    const int t0  = s * TCHUNK;
    const int t1  = (t0 + TCHUNK < 50) ? t0 + TCHUNK : 50;
    const int nt  = t1 - t0;
    const int tid = threadIdx.x;
    const float* xb = x + b * 784;

    // ---- P0: twiddles, Q, im2col (+ x_cnn output tail from slice 0) ----
    if (tid < 200) {
        float sn, cs;
        sincospif((float)tid * 0.01f, &sn, &cs);
        s_tw[tid] = make_float2(cs, -sn);
    }
    if (tid >= 256 && tid < 306) {
        int c = tid - 256;
        float num = fabsf(sinpif((float)(38 * (c + 1)) * 0.01f));
        float den = fabsf(sinpif((float)(c + 1) * 0.005f));
        s_Q[c] = num / den;
    }
    for (int idx = tid; idx < 1296; idx += THREADS) {
        int R = idx / 36, Cc = idx % 36;
        int r  = 5 * (R / 6) + Cc / 6;
        int cc = 5 * (R % 6) + Cc % 6;
        float v = 0.f;
        if (r >= 1 && r <= 28 && cc >= 1 && cc <= 28)
            v = xb[(r - 1) * 28 + (cc - 1)];
        s_x[idx] = v;
        if (s == 0) out[28800 + b * 1296 + idx] = v;
    }
    __syncthreads();

    // ---- P1 (disjoint thread ranges): WU for this slice  |  psi table ----
    if (tid < nt * 36) {
        // WU[tl][j] = |W[t,j]| * sum_i x_cnn[i,j] * tw[(50+2i)(2t-50) mod 200]
        int tl = tid / 36, j = tid % 36;
        int t  = t0 + tl;
        int d  = 2 * t - 50;
        int k    = ((50 * d) % 200 + 200) % 200;   // i = 0 phase
        int step = ((2  * d) % 200 + 200) % 200;   // increment per i
        const float* xc = &s_x[j];
        float ur = 0.f, ui = 0.f;
        #pragma unroll
        for (int i = 0; i < 36; i++) {
            float2 p = s_tw[k];
            float  xv = xc[i * 36];
            ur = fmaf(xv, p.x, ur);
            ui = fmaf(xv, p.y, ui);
            k += step; if (k >= 200) k -= 200;
        }
        float wv = fabsf(w[t * 36 + j]);
        s_B[tid] = make_float2(ur * wv, ui * wv);
    } else {
        for (int idx = tid - nt * 36; idx < 1800; idx += THREADS - nt * 36) {
            int c = idx / 36, j = idx % 36;
            int m = (76 * j * (c + 1)) % 200;
            s_psi[c * PHS + j] = s_tw[m];
        }
    }

    // ---- imax/wmax: every block computes both locally (no cross-block comm) ----
    float lm = 0.f, lw = 0.f;
    for (int idx = tid; idx < 1296; idx += THREADS) lm = fmaxf(lm, s_x[idx]);
    for (int idx = tid; idx < 1800; idx += THREADS) lw = fmaxf(lw, fabsf(w[idx]));
    float imax = bmax(lm, s_red);     // these syncs also fence the WU/psi writes
    float wmax = bmax(lw, s_red);

    // ---- P2: pass A for this slice's nt*50 points -> s_T + partial max ----
    float lT = 0.f;
    if (tid < nt * 50) {
        int tl = tid / 50, c = tid % 50;
        int t  = t0 + tl;
        const float2* wu = &s_B[tl * 36];
        const float2* ps = &s_psi[c * PHS];
        float vr = 0.f, vi = 0.f;
        #pragma unroll
        for (int j = 0; j < 36; j++) {
            float2 u = wu[j];
            float2 p = ps[j];
            vr = fmaf(p.x, u.x, vr); vr = fmaf(-p.y, u.y, vr);
            vi = fmaf(p.x, u.y, vi); vi = fmaf( p.y, u.x, vi);
        }
        float pt = 2.f * fabsf(cospif((float)(t - 25) * 0.01f));
        float a  = s_Q[c] * pt * sqrtf(vr * vr + vi * vi);
        s_T[tid] = a;
        lT = a;
    }
    float pm = bmax(lT, s_red);

    // ---- P3: cross-block max handshake (all 128 blocks co-resident) ----
    if (tid == 0) {
        atomicMax(&g_maxbits[b], __float_as_uint(pm));
        __threadfence();
        atomicAdd(&g_cnt[b], 1u);
        while (atomicAdd(&g_cnt[b], 0u) < SPLIT) __nanosleep(40);
        __threadfence();
        s_maxT = __uint_as_float(atomicAdd(&g_maxbits[b], 0u));
    }
    __syncthreads();
    float scale = imax * wmax / s_maxT;

    // ---- P4: write this slice's output rows: out[b, c, t0+tl] ----
    float* ob = out + b * 1800;
    for (int idx = tid; idx < 36 * nt; idx += THREADS) {
        int c = idx / nt, tl = idx % nt;
        int o = c * 50 + t0 + tl;
        ob[o] = s_T[tl * 50 + c] * scale + bias[o];
    }

    // ---- P5: replay-safe reset — 16th arrival clears the batch's slots ----
    if (tid == 0) {
        unsigned old = atomicAdd(&g_cnt[b], 1u);
        if (old == 2u * SPLIT - 1u) {
            atomicExch(&g_maxbits[b], 0u);
            atomicExch(&g_cnt[b], 0u);
        }
    }
}

extern "C" void kernel_launch(void* const* d_in, const int* in_sizes, int n_in,
                              void* d_out, int out_size)
{
    const float* x    = (const float*)d_in[0];  // (16,1,28,28)
    const float* w    = (const float*)d_in[1];  // (50,36)
    const float* bias = (const float*)d_in[2];  // (1,36,50)
    float* out = (float*)d_out;                 // 49536 floats
    ocnn_fused<<<16 * SPLIT, THREADS>>>(x, w, bias, out);
}

// round 8
// speedup vs baseline: 2.6143x; 1.1029x over previous
#include <cuda_runtime.h>
#include <math.h>

// Analytic collapse of the reference 4f-correlator FFT pipeline (verified, rel_err 3e-7):
//   |C[b,t,c]| = Qmag[c]*Pmag[t]*| sum_j psi(j,c)*|W[t,j]|*U[b,t,j] |
//   U[b,t,j]   = sum_i xcnn[b,i,j]*phi(i,t)
//   phi(i,t)   = tw[((50+2i)(2t-50)) mod 200],  tw[k] = exp(-i*pi*k/100)
//   psi(j,c)   = tw[(76*j*(c+1)) mod 200]
//   Pmag[t]    = 2|cos(pi*(t-25)/100)|
//   Qmag[c]    = |sin(pi*38(c+1)/100)| / |sin(pi*(c+1)/200)|
// out[b,c,t] = |C[b,t,c]| / max|C[b]| * imax[b]*wmax + bias[c,t];  then x_cnn appended.
//
// R8: 16 batches x 8 t-slices = 128 co-resident blocks; cross-block max via
// atomicMax + counter (pure spin, NO nanosleep). All gmem inputs prefetched in
// phase 0; imax/wmax as warp partials folded into the handshake; table-driven
// phi; 4-way split accumulator chains; ~6 barriers.

#define THREADS 512
#define SPLIT   8
#define TCHUNK  7
#define PHS     37            // padded row stride (float2) for psi

__device__ unsigned g_maxbits[16];   // per-batch max |C| (ordered uint), 0-init
__device__ unsigned g_cnt[16];       // per-batch arrival counter, 0-init

__global__ void __launch_bounds__(THREADS)
ocnn_fused(const float* __restrict__ x,      // (16,1,28,28)
           const float* __restrict__ w,      // (50,36)
           const float* __restrict__ bias,   // (1,36,50)
           float* __restrict__ out)          // [ (16,36,50) | (16,36,36) ]
{
    __shared__ float  s_xraw[784];
    __shared__ float  s_x[1296];
    __shared__ float2 s_tw[200];
    __shared__ float2 s_psi[50 * PHS];
    __shared__ float2 s_phi[TCHUNK * 36];
    __shared__ float2 s_B[TCHUNK * 36];
    __shared__ float  s_T[TCHUNK * 50];
    __shared__ float  s_Q[50];
    __shared__ float  s_Pt[TCHUNK];
    __shared__ float  s_im[16], s_wm[16];
    __shared__ float  s_red[16];
    __shared__ float  s_scale;

    const int b   = blockIdx.x >> 3;
    const int s   = blockIdx.x & (SPLIT - 1);
    const int t0  = s * TCHUNK;
    const int nt  = (t0 + TCHUNK <= 50) ? TCHUNK : 50 - t0;
    const int tid = threadIdx.x;
    const int lane = tid & 31, wid = tid >> 5;
    const float* xb = x + b * 784;

    // ================= Phase 0: prefetch + twiddles (no smem deps) =========
    float xv0 = __ldg(xb + tid);                                 // 0..511
    float xv1 = (tid < 272) ? __ldg(xb + 512 + tid) : 0.f;       // 512..783
    float w0 = fabsf(__ldg(w + tid));
    float w1 = fabsf(__ldg(w + 512 + tid));
    float w2 = fabsf(__ldg(w + 1024 + tid));
    float w3 = (tid < 264) ? fabsf(__ldg(w + 1536 + tid)) : 0.f;

    // per-thread tail values (WU weight, epilogue bias+index)
    float wuw = 0.f, bv = 0.f;
    int   o_out = 0;
    if (tid < nt * 36) {
        int tl = tid / 36, j = tid % 36;
        wuw = fabsf(__ldg(w + (t0 + tl) * 36 + j));
        int c_e = tid / nt, tl_e = tid % nt;      // epilogue owns same range
        o_out = c_e * 50 + t0 + tl_e;
        bv = __ldg(bias + o_out);
    }

    if (tid < 200) {
        float sn, cs;
        sincospif((float)tid * 0.01f, &sn, &cs);
        s_tw[tid] = make_float2(cs, -sn);
    }
    if (tid >= 256 && tid < 306) {
        int c = tid - 256;
        float num = fabsf(sinpif((float)(38 * (c + 1)) * 0.01f));
        float den = fabsf(sinpif((float)(c + 1) * 0.005f));
        s_Q[c] = num / den;
    }
    if (tid >= 320 && tid < 320 + nt)
        s_Pt[tid - 320] = 2.f * fabsf(cospif((float)(t0 + tid - 320 - 25) * 0.01f));

    s_xraw[tid] = xv0;
    if (tid < 272) s_xraw[512 + tid] = xv1;

    // imax/wmax warp partials (imax = max(x_cnn) = max(0, max(x)): padding zeros)
    float lm = fmaxf(fmaxf(xv0, xv1), 0.f);
    float lw = fmaxf(fmaxf(w0, w1), fmaxf(w2, w3));
    #pragma unroll
    for (int o = 16; o; o >>= 1) {
        lm = fmaxf(lm, __shfl_xor_sync(0xffffffffu, lm, o));
        lw = fmaxf(lw, __shfl_xor_sync(0xffffffffu, lw, o));
    }
    if (lane == 0) { s_im[wid] = lm; s_wm[wid] = lw; }
    __syncthreads();                                             // SYNC 1

    // ================= Phase 1: im2col + psi + phi tables ===================
    for (int idx = tid; idx < 1296; idx += THREADS) {
        int R = idx / 36, Cc = idx % 36;
        int r  = 5 * (R / 6) + Cc / 6;
        int cc = 5 * (R % 6) + Cc % 6;
        float v = 0.f;
        if (r >= 1 && r <= 28 && cc >= 1 && cc <= 28)
            v = s_xraw[(r - 1) * 28 + (cc - 1)];
        s_x[idx] = v;
        if (s == 0) out[28800 + b * 1296 + idx] = v;
    }
    for (int idx = tid; idx < 1800; idx += THREADS) {
        int c = idx / 36, j = idx % 36;
        s_psi[c * PHS + j] = s_tw[(76 * j * (c + 1)) % 200];
    }
    if (tid < nt * 36) {
        int tl = tid / 36, i = tid % 36;
        int k = ((50 + 2 * i) * (2 * (t0 + tl) - 50)) % 200;
        if (k < 0) k += 200;
        s_phi[tid] = s_tw[k];
    }
    __syncthreads();                                             // SYNC 2

    // ================= Phase 2: WU[tl][j] (4 accumulator chains) ===========
    if (tid < nt * 36) {
        int tl = tid / 36, j = tid % 36;
        const float2* ph = &s_phi[tl * 36];
        const float*  xc = &s_x[j];
        float ur0 = 0.f, ui0 = 0.f, ur1 = 0.f, ui1 = 0.f;
        #pragma unroll
        for (int i = 0; i < 36; i += 2) {
            float2 p0 = ph[i], p1 = ph[i + 1];
            float  x0 = xc[i * 36], x1 = xc[(i + 1) * 36];
            ur0 = fmaf(x0, p0.x, ur0); ui0 = fmaf(x0, p0.y, ui0);
            ur1 = fmaf(x1, p1.x, ur1); ui1 = fmaf(x1, p1.y, ui1);
        }
        s_B[tid] = make_float2((ur0 + ur1) * wuw, (ui0 + ui1) * wuw);
    }
    __syncthreads();                                             // SYNC 3

    // ================= Phase 3: pass A (4 chains) + block max ==============
    float lT = 0.f;
    if (tid < nt * 50) {
        int tl = tid / 50, c = tid % 50;
        const float2* wu = &s_B[tl * 36];
        const float2* ps = &s_psi[c * PHS];
        float vr0 = 0.f, vi0 = 0.f, vr1 = 0.f, vi1 = 0.f;
        #pragma unroll
        for (int j = 0; j < 36; j += 2) {
            float2 u0 = wu[j], p0 = ps[j];
            float2 u1 = wu[j + 1], p1 = ps[j + 1];
            vr0 = fmaf(p0.x, u0.x, vr0); vr0 = fmaf(-p0.y, u0.y, vr0);
            vi0 = fmaf(p0.x, u0.y, vi0); vi0 = fmaf( p0.y, u0.x, vi0);
            vr1 = fmaf(p1.x, u1.x, vr1); vr1 = fmaf(-p1.y, u1.y, vr1);
            vi1 = fmaf(p1.x, u1.y, vi1); vi1 = fmaf( p1.y, u1.x, vi1);
        }
        float vr = vr0 + vr1, vi = vi0 + vi1;
        float a = s_Q[c] * s_Pt[tl] * sqrtf(vr * vr + vi * vi);
        s_T[tid] = a;
        lT = a;
    }
    // block max of lT
    #pragma unroll
    for (int o = 16; o; o >>= 1)
        lT = fmaxf(lT, __shfl_xor_sync(0xffffffffu, lT, o));
    if (lane == 0) s_red[wid] = lT;
    __syncthreads();                                             // SYNC 4

    // ================= Phase 4: handshake (tid 0) ==========================
    if (tid == 0) {
        float pm = 0.f, im = 0.f, wm = 0.f;
        #pragma unroll
        for (int k = 0; k < 16; k++) {
            pm = fmaxf(pm, s_red[k]);
            im = fmaxf(im, s_im[k]);
            wm = fmaxf(wm, s_wm[k]);
        }
        atomicMax(&g_maxbits[b], __float_as_uint(pm));
        __threadfence();
        atomicAdd(&g_cnt[b], 1u);
        while (atomicAdd(&g_cnt[b], 0u) < SPLIT) { }             // pure spin
        __threadfence();
        float maxT = __uint_as_float(atomicAdd(&g_maxbits[b], 0u));
        s_scale = im * wm / maxT;
    }
    __syncthreads();                                             // SYNC 5

    // ================= Phase 5: epilogue (prefetched bias) =================
    if (tid < nt * 36) {
        int c = tid / nt, tl = tid % nt;
        out[b * 1800 + o_out] = fmaf(s_T[tl * 50 + c], s_scale, bv);
    }

    // replay-safe reset: 16th arrival clears this batch's slots
    if (tid == 0) {
        unsigned old = atomicAdd(&g_cnt[b], 1u);
        if (old == 2u * SPLIT - 1u) {
            atomicExch(&g_maxbits[b], 0u);
            atomicExch(&g_cnt[b], 0u);
        }
    }
}

extern "C" void kernel_launch(void* const* d_in, const int* in_sizes, int n_in,
                              void* d_out, int out_size)
{
    const float* x    = (const float*)d_in[0];  // (16,1,28,28)
    const float* w    = (const float*)d_in[1];  // (50,36)
    const float* bias = (const float*)d_in[2];  // (1,36,50)
    float* out = (float*)d_out;                 // 49536 floats
    ocnn_fused<<<16 * SPLIT, THREADS>>>(x, w, bias, out);
}